// round 4
// baseline (speedup 1.0000x reference)
#include <cuda_runtime.h>
#include <math.h>

// Problem constants
#define T_STEPS 1024
#define BATCH   64
#define DIM     768      // D == N == 768
#define NGATE   4        // gate order: 0=i, 1=f, 2=c(g), 3=o
#define NB_CTA  128
#define NTHR    256

// -------- device-global scratch (allocation-free rule: __device__ arrays) ----
// xproj layout: [T][G][B][N]
__device__ float g_xproj[(size_t)T_STEPS * NGATE * BATCH * DIM];
// transposed recurrent weights: [G][N][K] (contiguous K for coalesced staging)
__device__ float g_WrT[(size_t)NGATE * DIM * DIM];
// ping-pong hidden state + cell state
__device__ float g_h[2][BATCH * DIM];
__device__ float g_c[BATCH * DIM];
// grid-barrier counter (monotonic within a run; reset by init_state each run)
__device__ unsigned int g_bar;

// ---------------------------------------------------------------------------
__global__ void init_state(const float* __restrict__ h0, const float* __restrict__ c0) {
    int i = blockIdx.x * blockDim.x + threadIdx.x;
    if (i == 0) g_bar = 0u;
    if (i < BATCH * DIM) {
        g_h[0][i] = h0[i];
        g_c[i]    = c0[i];
    }
}

// ---------------------------------------------------------------------------
// transpose Wr[k][n] -> g_WrT[g][n][k].  grid (24, 24, 4), block (32, 8)
// ---------------------------------------------------------------------------
__global__ void transpose_wr(const float* __restrict__ w0, const float* __restrict__ w1,
                             const float* __restrict__ w2, const float* __restrict__ w3) {
    __shared__ float tile[32][33];
    int g = blockIdx.z;
    const float* W = (g == 0) ? w0 : (g == 1) ? w1 : (g == 2) ? w2 : w3;
    int n0 = blockIdx.x * 32;
    int k0 = blockIdx.y * 32;
    int tx = threadIdx.x, ty = threadIdx.y;

    #pragma unroll
    for (int i = ty; i < 32; i += 8)
        tile[i][tx] = W[(size_t)(k0 + i) * DIM + n0 + tx];
    __syncthreads();

    float* WT = g_WrT + (size_t)g * DIM * DIM;
    #pragma unroll
    for (int i = ty; i < 32; i += 8)
        WT[(size_t)(n0 + i) * DIM + k0 + tx] = tile[tx][i];
}

// ---------------------------------------------------------------------------
// Phase 1: input projections (unchanged from R2 — validated correct).
// 128x128x8 fp32 SGEMM, 256 threads, 8x8 microtile, double-buffered smem.
// grid (512, 6, 4)
// ---------------------------------------------------------------------------
__global__ __launch_bounds__(256) void input_proj(
        const float* __restrict__ x,
        const float* __restrict__ wk0, const float* __restrict__ wk1,
        const float* __restrict__ wk2, const float* __restrict__ wk3) {
    __shared__ float As[2][8][128];
    __shared__ float Bs[2][8][128];

    int g = blockIdx.z;
    const float* W = (g == 0) ? wk0 : (g == 1) ? wk1 : (g == 2) ? wk2 : wk3;
    int m0 = blockIdx.x * 128;
    int n0 = blockIdx.y * 128;
    int tid = threadIdx.x;
    int tx = tid & 15;
    int ty = tid >> 4;

    int ar = tid >> 1;
    int ak = (tid & 1) * 4;
    int bk = tid >> 5;
    int bc = (tid & 31) * 4;

    const float* aptr = x + (size_t)(m0 + ar) * DIM + ak;
    const float* bptr = W + (size_t)bk * DIM + n0 + bc;

    float4 a = *(const float4*)(aptr);
    float4 b = *(const float4*)(bptr);
    As[0][ak + 0][ar] = a.x; As[0][ak + 1][ar] = a.y;
    As[0][ak + 2][ar] = a.z; As[0][ak + 3][ar] = a.w;
    *(float4*)&Bs[0][bk][bc] = b;
    __syncthreads();

    float acc[8][8];
    #pragma unroll
    for (int i = 0; i < 8; ++i)
        #pragma unroll
        for (int j = 0; j < 8; ++j) acc[i][j] = 0.f;

    int buf = 0;
    for (int kt = 0; kt < 96; ++kt) {
        if (kt < 95) {
            int k0n = (kt + 1) * 8;
            a = *(const float4*)(aptr + k0n);
            b = *(const float4*)(bptr + (size_t)k0n * DIM);
        }
        #pragma unroll
        for (int kk = 0; kk < 8; ++kk) {
            float ra[8], rb[8];
            *(float4*)&ra[0] = *(float4*)&As[buf][kk][ty * 4];
            *(float4*)&ra[4] = *(float4*)&As[buf][kk][64 + ty * 4];
            *(float4*)&rb[0] = *(float4*)&Bs[buf][kk][tx * 4];
            *(float4*)&rb[4] = *(float4*)&Bs[buf][kk][64 + tx * 4];
            #pragma unroll
            for (int i = 0; i < 8; ++i)
                #pragma unroll
                for (int j = 0; j < 8; ++j)
                    acc[i][j] += ra[i] * rb[j];
        }
        if (kt < 95) {
            __syncthreads();
            buf ^= 1;
            As[buf][ak + 0][ar] = a.x; As[buf][ak + 1][ar] = a.y;
            As[buf][ak + 2][ar] = a.z; As[buf][ak + 3][ar] = a.w;
            *(float4*)&Bs[buf][bk][bc] = b;
            __syncthreads();
        }
    }

    #pragma unroll
    for (int i = 0; i < 8; ++i) {
        int m = m0 + ((i < 4) ? (ty * 4 + i) : (64 + ty * 4 + (i - 4)));
        int bb = m >> 10;          // batch (m = b*1024 + t)
        int tt = m & 1023;         // time
        float* dst = g_xproj + ((size_t)((tt * 4 + g) * 64 + bb)) * DIM + n0;
        float4 v0 = make_float4(acc[i][0], acc[i][1], acc[i][2], acc[i][3]);
        float4 v1 = make_float4(acc[i][4], acc[i][5], acc[i][6], acc[i][7]);
        *(float4*)(dst + tx * 4)      = v0;
        *(float4*)(dst + 64 + tx * 4) = v1;
    }
}

// ---------------------------------------------------------------------------
// Phase 2: persistent recurrence kernel. ONE graph node for all 1024 steps.
// 128 CTAs x 256 threads; CTA nb owns n-cols [nb*6, nb*6+6) for all 4 gates.
// Weights live in SMEM (duplicated {w,w} float2) for the whole kernel.
// Inner product uses fma.rn.f32x2: each thread = 2 batch rows x 3 weight cols.
// Steps separated by a software grid barrier (all 128 CTAs resident: 1/SM).
// ---------------------------------------------------------------------------
#define WS2_STRIDE 770     // float2 stride per weight col (pad: conflict-free)
#define HST_STRIDE 66      // floats per k-slice of transposed h (pad)
#define PRE_STRIDE 68      // floats per preact col (pad)
#define SMEM_FLOATS (24 * WS2_STRIDE * 2 + 64 * HST_STRIDE + 24 * PRE_STRIDE)
#define SMEM_BYTES  (SMEM_FLOATS * 4)

__device__ __forceinline__ void ffma2(unsigned long long& d,
                                      unsigned long long a, unsigned long long b) {
    asm("fma.rn.f32x2 %0, %1, %2, %0;" : "+l"(d) : "l"(a), "l"(b));
}

__device__ __forceinline__ void grid_sync(unsigned int target) {
    __syncthreads();
    if (threadIdx.x == 0) {
        __threadfence();                       // release this CTA's h/c writes
        atomicAdd(&g_bar, 1u);
        while (atomicAdd(&g_bar, 0u) < target) { }
        __threadfence();                       // acquire
    }
    __syncthreads();
}

__global__ __launch_bounds__(NTHR, 1) void lstm_persistent(float* __restrict__ out) {
    extern __shared__ float smem[];
    float2* Ws2 = (float2*)smem;                         // [24][WS2_STRIDE] of {w,w}
    float*  HsT = smem + 24 * WS2_STRIDE * 2;            // [64 k][HST_STRIDE rows]
    float*  pre = HsT + 64 * HST_STRIDE;                 // [24 col][PRE_STRIDE rows]

    const int nb  = blockIdx.x;        // 0..127
    const int tid = threadIdx.x;
    const int ct  = tid & 7;           // col tile: 3 cols each
    const int rt  = tid >> 3;          // row tile 0..31: 2 rows each
    const int r0  = rt * 2;

    // ---- stage duplicated weights ONCE (reused for all 1024 steps) ----
    for (int i = tid; i < 24 * 192; i += NTHR) {
        int c = i / 192, q = i - c * 192;
        int gg = c / 6, nl = c - gg * 6;
        const float4 v = *(const float4*)(g_WrT +
                          ((size_t)gg * DIM + nb * 6 + nl) * DIM + q * 4);
        float2* dst = Ws2 + (size_t)c * WS2_STRIDE + q * 4;
        dst[0] = make_float2(v.x, v.x);
        dst[1] = make_float2(v.y, v.y);
        dst[2] = make_float2(v.z, v.z);
        dst[3] = make_float2(v.w, v.w);
    }
    __syncthreads();

    const float2* w0p = Ws2 + (size_t)(ct * 3 + 0) * WS2_STRIDE;
    const float2* w1p = w0p + WS2_STRIDE;
    const float2* w2p = w1p + WS2_STRIDE;
    const float*  hTp = HsT + r0;

    for (int t = 0; t < T_STEPS; ++t) {
        const float* hbuf = g_h[t & 1];
        unsigned long long a0 = 0ull, a1 = 0ull, a2 = 0ull;

        for (int kt = 0; kt < 12; ++kt) {
            const int k0 = kt * 64;
            __syncthreads();   // protect previous tile's HsT reads
            // stage HsT[k][row] = h[row][k0+k]  (L1-bypass: h is cross-CTA data)
            for (int i = tid; i < 1024; i += NTHR) {
                int q = i & 15, r = i >> 4;
                float4 v = __ldcg((const float4*)(hbuf + r * DIM + k0 + q * 4));
                float* d = HsT + (q * 4) * HST_STRIDE + r;
                d[0 * HST_STRIDE] = v.x;
                d[1 * HST_STRIDE] = v.y;
                d[2 * HST_STRIDE] = v.z;
                d[3 * HST_STRIDE] = v.w;
            }
            __syncthreads();
            #pragma unroll 8
            for (int kk = 0; kk < 64; ++kk) {
                unsigned long long h2 =
                    *(const unsigned long long*)(hTp + (size_t)kk * HST_STRIDE);
                unsigned long long w0 = *(const unsigned long long*)(w0p + k0 + kk);
                unsigned long long w1 = *(const unsigned long long*)(w1p + k0 + kk);
                unsigned long long w2 = *(const unsigned long long*)(w2p + k0 + kk);
                ffma2(a0, h2, w0);
                ffma2(a1, h2, w1);
                ffma2(a2, h2, w2);
            }
        }

        // preact = recurrent acc + input projection -> pre[col][row]
        {
            unsigned long long accs[3] = {a0, a1, a2};
            #pragma unroll
            for (int j = 0; j < 3; ++j) {
                int c  = ct * 3 + j;
                int gg = c / 6, nl = c - gg * 6;
                int n  = nb * 6 + nl;
                const float* xp = g_xproj + ((size_t)((t * 4 + gg) * 64)) * DIM + n;
                float lo, hi;
                asm("mov.b64 {%0, %1}, %2;" : "=f"(lo), "=f"(hi) : "l"(accs[j]));
                pre[c * PRE_STRIDE + r0 + 0] = lo + xp[(size_t)(r0 + 0) * DIM];
                pre[c * PRE_STRIDE + r0 + 1] = hi + xp[(size_t)(r0 + 1) * DIM];
            }
        }
        __syncthreads();

        // gate update for this CTA's (b, n) slice: 64 rows x 6 n-cols
        float* hnew = g_h[(t + 1) & 1];
        for (int i = tid; i < 64 * 6; i += NTHR) {
            int bb = i & 63;
            int nl = i >> 6;               // 0..5
            float xi = pre[(0 * 6 + nl) * PRE_STRIDE + bb];
            float xf = pre[(1 * 6 + nl) * PRE_STRIDE + bb];
            float xg = pre[(2 * 6 + nl) * PRE_STRIDE + bb];
            float xo = pre[(3 * 6 + nl) * PRE_STRIDE + bb];
            int n = nb * 6 + nl;
            float ii = fminf(fmaxf(0.2f * xi + 0.5f, 0.f), 1.f);
            float ff = fminf(fmaxf(0.2f * xf + 0.5f, 0.f), 1.f);
            float oo = fminf(fmaxf(0.2f * xo + 0.5f, 0.f), 1.f);
            float gg2 = tanhf(xg);
            float cold = g_c[bb * DIM + n];       // CTA-private slice: L1 safe
            float cn = cold * ff + ii * gg2;
            float hn = tanhf(cn) * oo;
            g_c[bb * DIM + n] = cn;
            hnew[bb * DIM + n] = hn;
            out[((size_t)bb * T_STEPS + t) * DIM + n] = hn;
        }

        grid_sync((unsigned)(t + 1) * NB_CTA);
    }
}

// ---------------------------------------------------------------------------
extern "C" void kernel_launch(void* const* d_in, const int* in_sizes, int n_in,
                              void* d_out, int out_size) {
    const float* x   = (const float*)d_in[0];
    const float* h0  = (const float*)d_in[1];
    const float* c0  = (const float*)d_in[2];
    const float* Wki = (const float*)d_in[3];
    const float* Wri = (const float*)d_in[4];
    const float* Wkf = (const float*)d_in[5];
    const float* Wrf = (const float*)d_in[6];
    const float* Wkc = (const float*)d_in[7];
    const float* Wrc = (const float*)d_in[8];
    const float* Wko = (const float*)d_in[9];
    const float* Wro = (const float*)d_in[10];
    float* out = (float*)d_out;

    // idempotent; executes immediately (not a stream op), capture-safe
    cudaFuncSetAttribute(lstm_persistent,
                         cudaFuncAttributeMaxDynamicSharedMemorySize, SMEM_BYTES);

    init_state<<<(BATCH * DIM + 255) / 256, 256>>>(h0, c0);
    transpose_wr<<<dim3(24, 24, 4), dim3(32, 8)>>>(Wri, Wrf, Wrc, Wro);
    input_proj<<<dim3(512, 6, 4), 256>>>(x, Wki, Wkf, Wkc, Wko);
    lstm_persistent<<<NB_CTA, NTHR, SMEM_BYTES>>>(out);
}

// round 5
// speedup vs baseline: 2.6468x; 2.6468x over previous
#include <cuda_runtime.h>
#include <math.h>

// Problem constants
#define T_STEPS 1024
#define BATCH   64
#define DIM     768      // D == N == 768
#define NB_CTA  128
#define NTHR    256

// -------- device-global scratch (allocation-free rule: __device__ arrays) ----
__device__ float g_xproj [(size_t)T_STEPS * 4 * BATCH * DIM];  // [t][g][b][n]
__device__ float g_xprojT[(size_t)T_STEPS * 4 * DIM * BATCH];  // [t][g][n][b]
__device__ float g_WrT[(size_t)4 * DIM * DIM];                 // [g][n][k]
__device__ float g_hT[2][DIM * BATCH];                         // [n][b] ping-pong
__device__ float g_cT[DIM * BATCH];                            // [n][b]
__device__ unsigned int g_bar;

// ---------------------------------------------------------------------------
__global__ void init_state(const float* __restrict__ h0, const float* __restrict__ c0) {
    int i = blockIdx.x * blockDim.x + threadIdx.x;
    if (i == 0) g_bar = 0u;
    if (i < DIM * BATCH) {
        int n = i >> 6, bb = i & 63;
        g_hT[0][i] = h0[bb * DIM + n];
        g_cT[i]    = c0[bb * DIM + n];
    }
}

// ---------------------------------------------------------------------------
// transpose Wr[k][n] -> g_WrT[g][n][k].  grid (24, 24, 4), block (32, 8)
// ---------------------------------------------------------------------------
__global__ void transpose_wr(const float* __restrict__ w0, const float* __restrict__ w1,
                             const float* __restrict__ w2, const float* __restrict__ w3) {
    __shared__ float tile[32][33];
    int g = blockIdx.z;
    const float* W = (g == 0) ? w0 : (g == 1) ? w1 : (g == 2) ? w2 : w3;
    int n0 = blockIdx.x * 32;
    int k0 = blockIdx.y * 32;
    int tx = threadIdx.x, ty = threadIdx.y;

    #pragma unroll
    for (int i = ty; i < 32; i += 8)
        tile[i][tx] = W[(size_t)(k0 + i) * DIM + n0 + tx];
    __syncthreads();

    float* WT = g_WrT + (size_t)g * DIM * DIM;
    #pragma unroll
    for (int i = ty; i < 32; i += 8)
        WT[(size_t)(n0 + i) * DIM + k0 + tx] = tile[tx][i];
}

// ---------------------------------------------------------------------------
// FFMA2 helper (fma.rn.f32x2 — packed 2x fp32 FMA, PTX-only on sm_103a)
// ---------------------------------------------------------------------------
__device__ __forceinline__ void ffma2(unsigned long long& d,
                                      unsigned long long a, unsigned long long b) {
    asm("fma.rn.f32x2 %0, %1, %2, %0;" : "+l"(d) : "l"(a), "l"(b));
}

// ---------------------------------------------------------------------------
// Phase 1: input projections with FFMA2 (2 m-rows packed per accumulator).
// 128x128x8 tile, 256 threads. Thread microtile: 4 row-pairs x 8 cols, both
// strided by 16 so A/B smem reads are conflict-free.
// Output layout [t][g][b][n] (coalesced float-ish stores; transposed later).
// grid (512, 6, 4)
// ---------------------------------------------------------------------------
__global__ __launch_bounds__(256) void input_proj(
        const float* __restrict__ x,
        const float* __restrict__ wk0, const float* __restrict__ wk1,
        const float* __restrict__ wk2, const float* __restrict__ wk3) {
    __shared__ __align__(16) float As[2][8][128];   // As[buf][k][m] (pairs = consecutive m)
    __shared__ __align__(16) float Bs[2][8][256];   // duplicated {w,w} per n

    int g = blockIdx.z;
    const float* W = (g == 0) ? wk0 : (g == 1) ? wk1 : (g == 2) ? wk2 : wk3;
    int m0 = blockIdx.x * 128;
    int n0 = blockIdx.y * 128;
    int tid = threadIdx.x;
    int tx = tid & 15;          // n base
    int ty = tid >> 4;          // row-pair base (0..15)

    int ar = tid >> 1, ak = (tid & 1) * 4;
    int bk = tid >> 5, bc = (tid & 31) * 4;

    const float* aptr = x + (size_t)(m0 + ar) * DIM + ak;
    const float* bptr = W + (size_t)bk * DIM + n0 + bc;

    float4 a = *(const float4*)(aptr);
    float4 b = *(const float4*)(bptr);
    As[0][ak + 0][ar] = a.x; As[0][ak + 1][ar] = a.y;
    As[0][ak + 2][ar] = a.z; As[0][ak + 3][ar] = a.w;
    *(float2*)&Bs[0][bk][2 * (bc + 0)] = make_float2(b.x, b.x);
    *(float2*)&Bs[0][bk][2 * (bc + 1)] = make_float2(b.y, b.y);
    *(float2*)&Bs[0][bk][2 * (bc + 2)] = make_float2(b.z, b.z);
    *(float2*)&Bs[0][bk][2 * (bc + 3)] = make_float2(b.w, b.w);
    __syncthreads();

    unsigned long long acc[4][8];
    #pragma unroll
    for (int i = 0; i < 4; ++i)
        #pragma unroll
        for (int j = 0; j < 8; ++j) acc[i][j] = 0ull;

    int buf = 0;
    for (int kt = 0; kt < 96; ++kt) {
        if (kt < 95) {
            int k0n = (kt + 1) * 8;
            a = *(const float4*)(aptr + k0n);
            b = *(const float4*)(bptr + (size_t)k0n * DIM);
        }
        #pragma unroll
        for (int kk = 0; kk < 8; ++kk) {
            unsigned long long a2[4], b2[8];
            #pragma unroll
            for (int i = 0; i < 4; ++i)
                a2[i] = *(const unsigned long long*)&As[buf][kk][2 * (ty + 16 * i)];
            #pragma unroll
            for (int j = 0; j < 8; ++j)
                b2[j] = *(const unsigned long long*)&Bs[buf][kk][2 * (tx + 16 * j)];
            #pragma unroll
            for (int i = 0; i < 4; ++i)
                #pragma unroll
                for (int j = 0; j < 8; ++j)
                    ffma2(acc[i][j], a2[i], b2[j]);
        }
        if (kt < 95) {
            __syncthreads();
            buf ^= 1;
            As[buf][ak + 0][ar] = a.x; As[buf][ak + 1][ar] = a.y;
            As[buf][ak + 2][ar] = a.z; As[buf][ak + 3][ar] = a.w;
            *(float2*)&Bs[buf][bk][2 * (bc + 0)] = make_float2(b.x, b.x);
            *(float2*)&Bs[buf][bk][2 * (bc + 1)] = make_float2(b.y, b.y);
            *(float2*)&Bs[buf][bk][2 * (bc + 2)] = make_float2(b.z, b.z);
            *(float2*)&Bs[buf][bk][2 * (bc + 3)] = make_float2(b.w, b.w);
            __syncthreads();
        }
    }

    // store: pair i -> rows m0+2*(ty+16i), +1 ; col j -> n0 + tx + 16j
    #pragma unroll
    for (int i = 0; i < 4; ++i) {
        int m_lo = m0 + 2 * (ty + 16 * i);
        int bb = m_lo >> 10;             // m = b*1024 + t
        int tt = m_lo & 1023;            // even; tt+1 stays in same b-block
        float* base_lo = g_xproj + ((size_t)((tt * 4 + g) * 64 + bb)) * DIM + n0;
        float* base_hi = g_xproj + ((size_t)(((tt + 1) * 4 + g) * 64 + bb)) * DIM + n0;
        #pragma unroll
        for (int j = 0; j < 8; ++j) {
            float lo, hi;
            asm("mov.b64 {%0,%1}, %2;" : "=f"(lo), "=f"(hi) : "l"(acc[i][j]));
            base_lo[tx + 16 * j] = lo;
            base_hi[tx + 16 * j] = hi;
        }
    }
}

// ---------------------------------------------------------------------------
// xproj [t][g][b][n] -> xprojT [t][g][n][b].  grid (12, 1024, 4), block 256.
// ---------------------------------------------------------------------------
__global__ __launch_bounds__(256) void transpose_x() {
    __shared__ float tile[64][65];
    int n0 = blockIdx.x * 64;
    int t  = blockIdx.y, g = blockIdx.z;
    const float* src = g_xproj  + (size_t)(t * 4 + g) * 64 * DIM;
    float*       dst = g_xprojT + (size_t)(t * 4 + g) * DIM * 64;
    int tid = threadIdx.x;
    for (int i = tid; i < 4096; i += 256) {
        int nl = i & 63, bb = i >> 6;
        tile[nl][bb] = src[(size_t)bb * DIM + n0 + nl];
    }
    __syncthreads();
    for (int i = tid; i < 4096; i += 256) {
        int bb = i & 63, nl = i >> 6;
        dst[(size_t)(n0 + nl) * 64 + bb] = tile[nl][bb];
    }
}

// ---------------------------------------------------------------------------
// Phase 2: persistent recurrence. 128 CTAs x 256 threads, 1 CTA/SM.
// Thread tile: 4 batch-pairs (8 rows) x 6 cols (one gate's 6 n-cols),
// warp-level k-split by 8 (kk === warp_kp mod 8), reduced through smem.
// h kept in [n][b] layout globally -> slice staging is a straight copy.
// Weights duplicated {w,w} in smem for the whole kernel (col pad 770 f2).
// ---------------------------------------------------------------------------
#define WS_COL 770                                  // float2 per weight col (pad)
#define OFF_SCRATCH (24 * WS_COL * 2)               // 36960 floats
#define OFF_PRE     (OFF_SCRATCH + 16384)           // after 2x8192 H2 buffers
#define OFF_STASH   (OFF_PRE + 24 * 64)
#define SMEM_FLOATS (OFF_STASH + 64 * 9)
#define SMEM_BYTES  (SMEM_FLOATS * 4)               // 221824 B

__device__ __forceinline__ void grid_sync(unsigned int target) {
    __syncthreads();
    if (threadIdx.x == 0) {
        __threadfence();
        atomicAdd(&g_bar, 1u);
        while (atomicAdd(&g_bar, 0u) < target) { }
        __threadfence();
    }
    __syncthreads();
}

__global__ __launch_bounds__(NTHR, 1) void lstm_persistent(float* __restrict__ out) {
    extern __shared__ float smem[];
    float2* Ws2    = (float2*)smem;                  // [24][WS_COL] dup weights
    float* scratch = smem + OFF_SCRATCH;             // 2x H2 buffers / red alias
    float* pre     = smem + OFF_PRE;                 // [24][64] preactivations
    float* stash   = smem + OFF_STASH;               // [64][9] h for out-writes

    const int nb  = blockIdx.x;
    const int tid = threadIdx.x;
    const int rt  = tid & 7;            // batch-pair base (pairs rt+8j)
    const int ct  = (tid >> 3) & 3;     // gate (0..3)
    const int kp  = tid >> 5;           // k-partition == warp id (0..7)

    // ---- stage duplicated weights once (reused for all 1024 steps) ----
    for (int i = tid; i < 24 * 192; i += NTHR) {
        int c = i / 192, q = i - c * 192;
        int g = c / 6, nl = c - g * 6;
        float4 v = *(const float4*)(g_WrT + ((size_t)g * DIM + nb * 6 + nl) * DIM + q * 4);
        float2* dst = Ws2 + c * WS_COL + q * 4;
        dst[0] = make_float2(v.x, v.x);
        dst[1] = make_float2(v.y, v.y);
        dst[2] = make_float2(v.z, v.z);
        dst[3] = make_float2(v.w, v.w);
    }
    __syncthreads();

    const unsigned long long* wbase =
        (const unsigned long long*)(Ws2 + ct * 6 * WS_COL);

    for (int t = 0; t < T_STEPS; ++t) {
        const float* hT = g_hT[t & 1];
        unsigned long long acc[6][4];
        #pragma unroll
        for (int cj = 0; cj < 6; ++cj)
            #pragma unroll
            for (int pj = 0; pj < 4; ++pj) acc[cj][pj] = 0ull;

        // prologue: stage k-slice 0 (straight copy — hT is [n][b])
        {
            const float4* src = (const float4*)hT;
            float4* d = (float4*)scratch;
            #pragma unroll
            for (int q = 0; q < 8; ++q) d[q * NTHR + tid] = __ldcg(src + q * NTHR + tid);
        }
        __syncthreads();

        for (int kt = 0; kt < 6; ++kt) {
            float4 r[8];
            if (kt < 5) {
                const float4* src = (const float4*)(hT + (kt + 1) * 128 * 64);
                #pragma unroll
                for (int q = 0; q < 8; ++q) r[q] = __ldcg(src + q * NTHR + tid);
            }
            const unsigned long long* h2 =
                (const unsigned long long*)(scratch + (kt & 1) * 8192);
            const int k0 = kt * 128;
            #pragma unroll 4
            for (int m = 0; m < 16; ++m) {
                int kk = kp + (m << 3);
                unsigned long long hr[4];
                #pragma unroll
                for (int pj = 0; pj < 4; ++pj)
                    hr[pj] = h2[kk * 32 + rt + (pj << 3)];
                #pragma unroll
                for (int cj = 0; cj < 6; ++cj) {
                    unsigned long long w = wbase[cj * WS_COL + k0 + kk];
                    #pragma unroll
                    for (int pj = 0; pj < 4; ++pj) ffma2(acc[cj][pj], hr[pj], w);
                }
            }
            if (kt < 5) {
                float4* d = (float4*)(scratch + ((kt + 1) & 1) * 8192);
                #pragma unroll
                for (int q = 0; q < 8; ++q) d[q * NTHR + tid] = r[q];
            }
            __syncthreads();
        }

        // ---- k-partition reduction via smem (red aliases dead H2 buffers) ----
        float2* red = (float2*)scratch;              // [8][24][33]
        #pragma unroll
        for (int cj = 0; cj < 6; ++cj)
            #pragma unroll
            for (int pj = 0; pj < 4; ++pj) {
                float lo, hi;
                asm("mov.b64 {%0,%1}, %2;" : "=f"(lo), "=f"(hi) : "l"(acc[cj][pj]));
                red[kp * 792 + (ct * 6 + cj) * 33 + rt + (pj << 3)] = make_float2(lo, hi);
            }
        __syncthreads();

        #pragma unroll
        for (int u = 0; u < 3; ++u) {
            int o = tid + u * NTHR;                  // 0..767
            int c = o >> 5, p = o & 31;
            float2 s = red[c * 33 + p];
            #pragma unroll
            for (int k2 = 1; k2 < 8; ++k2) {
                float2 v = red[k2 * 792 + c * 33 + p];
                s.x += v.x; s.y += v.y;
            }
            int g = c / 6, nl = c - g * 6;
            const float2* xp = (const float2*)(g_xprojT +
                ((size_t)((t * 4 + g) * DIM) + nb * 6 + nl) * 64);
            float2 xv = __ldg(xp + p);
            s.x += xv.x; s.y += xv.y;
            *(float2*)(pre + c * 64 + 2 * p) = s;
        }
        __syncthreads();

        // ---- gate update: 64 batch x 6 n-cols (CTA-private slice) ----
        float* hTn = g_hT[(t + 1) & 1];
        for (int i = tid; i < 384; i += NTHR) {
            int bb = i & 63, j = i >> 6;
            float xi = pre[(0 * 6 + j) * 64 + bb];
            float xf = pre[(1 * 6 + j) * 64 + bb];
            float xg = pre[(2 * 6 + j) * 64 + bb];
            float xo = pre[(3 * 6 + j) * 64 + bb];
            int n = nb * 6 + j;
            float ii  = fminf(fmaxf(0.2f * xi + 0.5f, 0.f), 1.f);
            float ff  = fminf(fmaxf(0.2f * xf + 0.5f, 0.f), 1.f);
            float oo  = fminf(fmaxf(0.2f * xo + 0.5f, 0.f), 1.f);
            float gg2 = tanhf(xg);
            float cold = g_cT[n * 64 + bb];
            float cn = cold * ff + ii * gg2;
            float hn = tanhf(cn) * oo;
            g_cT[n * 64 + bb] = cn;
            __stcg(hTn + n * 64 + bb, hn);           // cross-CTA: bypass L1
            stash[bb * 9 + j] = hn;
        }
        __syncthreads();
        for (int i = tid; i < 384; i += NTHR) {
            int bb = i / 6, j = i - bb * 6;
            out[(size_t)bb * (T_STEPS * DIM) + (size_t)t * DIM + nb * 6 + j] =
                stash[bb * 9 + j];
        }

        grid_sync((unsigned)(t + 1) * NB_CTA);
    }
}

// ---------------------------------------------------------------------------
extern "C" void kernel_launch(void* const* d_in, const int* in_sizes, int n_in,
                              void* d_out, int out_size) {
    const float* x   = (const float*)d_in[0];
    const float* h0  = (const float*)d_in[1];
    const float* c0  = (const float*)d_in[2];
    const float* Wki = (const float*)d_in[3];
    const float* Wri = (const float*)d_in[4];
    const float* Wkf = (const float*)d_in[5];
    const float* Wrf = (const float*)d_in[6];
    const float* Wkc = (const float*)d_in[7];
    const float* Wrc = (const float*)d_in[8];
    const float* Wko = (const float*)d_in[9];
    const float* Wro = (const float*)d_in[10];
    float* out = (float*)d_out;

    cudaFuncSetAttribute(lstm_persistent,
                         cudaFuncAttributeMaxDynamicSharedMemorySize, SMEM_BYTES);

    init_state<<<192, 256>>>(h0, c0);
    transpose_wr<<<dim3(24, 24, 4), dim3(32, 8)>>>(Wri, Wrf, Wrc, Wro);
    input_proj<<<dim3(512, 6, 4), 256>>>(x, Wki, Wkf, Wkc, Wko);
    transpose_x<<<dim3(12, 1024, 4), 256>>>();
    lstm_persistent<<<NB_CTA, NTHR, SMEM_BYTES>>>(out);
}